// round 1
// baseline (speedup 1.0000x reference)
#include <cuda_runtime.h>
#include <cuda_bf16.h>
#include <cstdint>

// ---------------------------------------------------------------------------
// Only the g_list[0] branch matters for the output (g_list[1] branch is dead):
//   nf0 = sqrt(2/64)*cos(feat0 @ W_rbf0 + b_rbf0)              [N0,64]
//   conv1 (H=2,F=8): t1 = nf0@W1; GAT softmax scatter; relu    [N0,16]
//   conv2 (H=1,F=64): t2 = x1@W2; GAT softmax scatter          [N0,64]
//   mean over nodes -> relu -> fc1 -> relu -> out              [1]
// ---------------------------------------------------------------------------

#define N0C 200000
#define E0C 1000000

__device__ __align__(16) float d_nf0[(size_t)N0C * 64];
__device__ __align__(16) float d_t1[(size_t)N0C * 16];
__device__ float d_el1[N0C * 2];
__device__ float d_er1[N0C * 2];
__device__ float d_emax1[N0C * 2];
__device__ float d_denom1[N0C * 2];
__device__ __align__(16) float d_num1[(size_t)N0C * 16];
__device__ float d_e1[(size_t)E0C * 2];
__device__ __align__(16) float d_x1[(size_t)N0C * 16];
__device__ __align__(16) float d_t2[(size_t)N0C * 64];
__device__ float d_el2[N0C];
__device__ float d_er2[N0C];
__device__ float d_emax2[N0C];
__device__ float d_denom2[N0C];
__device__ __align__(16) float d_num2[(size_t)N0C * 64];
__device__ float d_e2[E0C];
__device__ float d_acc[64];

// sign-aware float atomic max (works for mixed-sign values, init = -inf)
__device__ __forceinline__ void atomicMaxF(float* addr, float v) {
    if (v >= 0.0f) {
        atomicMax((int*)addr, __float_as_int(v));
    } else {
        atomicMin((unsigned int*)addr, (unsigned int)__float_as_int(v));
    }
}

// vectorized global reduction (sm_90+): 4 floats per op
__device__ __forceinline__ void redAdd4(float* addr, float x, float y, float z, float w) {
    asm volatile("red.global.add.v4.f32 [%0], {%1, %2, %3, %4};"
                 :: "l"(addr), "f"(x), "f"(y), "f"(z), "f"(w) : "memory");
}

__device__ __forceinline__ float leaky02(float x) {
    return x >= 0.0f ? x : 0.2f * x;
}

// ---------------------------------------------------------------------------
__global__ void k_init(int n0) {
    const float NEG_INF = __int_as_float(0xff800000);
    int i = blockIdx.x * blockDim.x + threadIdx.x;
    int stride = gridDim.x * blockDim.x;
    for (int k = i; k < n0 * 2; k += stride) { d_emax1[k] = NEG_INF; d_denom1[k] = 0.0f; }
    for (int k = i; k < n0; k += stride) { d_emax2[k] = NEG_INF; d_denom2[k] = 0.0f; }
    for (int k = i; k < n0 * 16; k += stride) d_num1[k] = 0.0f;
    for (size_t k = i; k < (size_t)n0 * 64; k += stride) d_num2[k] = 0.0f;
    if (i < 64) d_acc[i] = 0.0f;
}

// RBF features: nf0[n,j] = sqrt(2/64)*cos(sum_k feat0[n,k]*Wrbf[k,j] + brbf[j])
// block = 256 threads = 4 nodes x 64 output cols
__global__ void k_rbf(const float* __restrict__ feat0, const float* __restrict__ Wrbf,
                      const float* __restrict__ brbf, int n0) {
    __shared__ float sfeat[4][62];
    int grp = threadIdx.x >> 6;        // 0..3
    int j = threadIdx.x & 63;          // 0..63
    int node = blockIdx.x * 4 + grp;
    int g = threadIdx.x;
    if (g < 4 * 62) {
        int nn = g / 62, kk = g % 62;
        int nd = blockIdx.x * 4 + nn;
        sfeat[nn][kk] = (nd < n0) ? feat0[(size_t)nd * 62 + kk] : 0.0f;
    }
    __syncthreads();
    if (node >= n0) return;
    float acc = brbf[j];
#pragma unroll
    for (int k = 0; k < 62; k++) acc = fmaf(sfeat[grp][k], Wrbf[k * 64 + j], acc);
    d_nf0[(size_t)node * 64 + j] = 0.17677669529663687f * cosf(acc);
}

// t1 = nf0 @ W1 [64x16], plus el1/er1 per (node, head)
// block = 256 threads = 16 nodes x 16 outputs
__global__ void k_t1(const float* __restrict__ W1, const float* __restrict__ al,
                     const float* __restrict__ ar, int n0) {
    __shared__ float s_nf[16][64];
    __shared__ float s_t[16][16];
    int nodeBase = blockIdx.x * 16;
    for (int i = threadIdx.x; i < 16 * 64; i += 256) {
        int nn = i >> 6, kk = i & 63;
        int nd = nodeBase + nn;
        s_nf[nn][kk] = (nd < n0) ? d_nf0[(size_t)nd * 64 + kk] : 0.0f;
    }
    __syncthreads();
    int nn = threadIdx.x >> 4, hf = threadIdx.x & 15;
    int node = nodeBase + nn;
    float acc = 0.0f;
#pragma unroll
    for (int k = 0; k < 64; k++) acc = fmaf(s_nf[nn][k], W1[k * 16 + hf], acc);
    s_t[nn][hf] = acc;
    if (node < n0) d_t1[(size_t)node * 16 + hf] = acc;
    __syncthreads();
    if (hf < 2 && node < n0) {
        int h = hf;
        float el = 0.0f, er = 0.0f;
#pragma unroll
        for (int f = 0; f < 8; f++) {
            float t = s_t[nn][h * 8 + f];
            el = fmaf(t, al[h * 8 + f], el);
            er = fmaf(t, ar[h * 8 + f], er);
        }
        d_el1[node * 2 + h] = el;
        d_er1[node * 2 + h] = er;
    }
}

// conv1 edge pass A: e = leaky(el[s]+er[d]); segment max via atomics; stash e
__global__ void k_emax1(const int* __restrict__ src, const int* __restrict__ dst, int e0) {
    int i = blockIdx.x * blockDim.x + threadIdx.x;
    if (i >= e0) return;
    int s = src[i], d = dst[i];
#pragma unroll
    for (int h = 0; h < 2; h++) {
        float e = leaky02(d_el1[s * 2 + h] + d_er1[d * 2 + h]);
        d_e1[(size_t)i * 2 + h] = e;
        atomicMaxF(&d_emax1[d * 2 + h], e);
    }
}

// conv1 edge pass B: a = exp(e - emax[d]); scatter denom & num (vector red)
__global__ void k_esum1(const int* __restrict__ src, const int* __restrict__ dst, int e0) {
    int i = blockIdx.x * blockDim.x + threadIdx.x;
    if (i >= e0) return;
    int s = src[i], d = dst[i];
#pragma unroll
    for (int h = 0; h < 2; h++) {
        float a = expf(d_e1[(size_t)i * 2 + h] - d_emax1[d * 2 + h]);
        atomicAdd(&d_denom1[d * 2 + h], a);
        const float4* tp = (const float4*)(d_t1 + (size_t)s * 16 + h * 8);
        float4 v0 = tp[0], v1 = tp[1];
        float* np = d_num1 + (size_t)d * 16 + h * 8;
        redAdd4(np, a * v0.x, a * v0.y, a * v0.z, a * v0.w);
        redAdd4(np + 4, a * v1.x, a * v1.y, a * v1.z, a * v1.w);
    }
}

// conv1 epilogue: x1 = relu(num/max(denom,1e-9) + b)
__global__ void k_x1(const float* __restrict__ b1, int n0) {
    int i = blockIdx.x * blockDim.x + threadIdx.x;
    if (i >= n0 * 16) return;
    int n = i >> 4, hf = i & 15, h = hf >> 3;
    float den = fmaxf(d_denom1[n * 2 + h], 1e-9f);
    float v = d_num1[i] / den + b1[hf];
    d_x1[i] = fmaxf(v, 0.0f);
}

// t2 = x1 @ W2 [16x64], plus el2/er2 (single head)
// block = 256 = 4 nodes x 64 cols
__global__ void k_t2(const float* __restrict__ W2, const float* __restrict__ al2,
                     const float* __restrict__ ar2, int n0) {
    __shared__ float sx[4][16];
    __shared__ float spart[4][2][2];
    int grp = threadIdx.x >> 6;
    int j = threadIdx.x & 63;
    int node = blockIdx.x * 4 + grp;
    if (threadIdx.x < 64) {
        int nn = threadIdx.x >> 4, kk = threadIdx.x & 15;
        int nd = blockIdx.x * 4 + nn;
        sx[nn][kk] = (nd < n0) ? d_x1[(size_t)nd * 16 + kk] : 0.0f;
    }
    __syncthreads();
    float acc = 0.0f;
#pragma unroll
    for (int k = 0; k < 16; k++) acc = fmaf(sx[grp][k], W2[k * 64 + j], acc);
    if (node < n0) d_t2[(size_t)node * 64 + j] = acc;
    float pl = acc * al2[j], pr = acc * ar2[j];
#pragma unroll
    for (int off = 16; off; off >>= 1) {
        pl += __shfl_down_sync(0xffffffff, pl, off);
        pr += __shfl_down_sync(0xffffffff, pr, off);
    }
    int half = j >> 5;
    if ((threadIdx.x & 31) == 0) { spart[grp][half][0] = pl; spart[grp][half][1] = pr; }
    __syncthreads();
    if (j == 0 && node < n0) {
        d_el2[node] = spart[grp][0][0] + spart[grp][1][0];
        d_er2[node] = spart[grp][0][1] + spart[grp][1][1];
    }
}

// conv2 edge pass A
__global__ void k_emax2(const int* __restrict__ src, const int* __restrict__ dst, int e0) {
    int i = blockIdx.x * blockDim.x + threadIdx.x;
    if (i >= e0) return;
    int s = src[i], d = dst[i];
    float e = leaky02(d_el2[s] + d_er2[d]);
    d_e2[i] = e;
    atomicMaxF(&d_emax2[d], e);
}

// conv2 edge pass B: 16 lanes per edge, each handles one float4 of the 64-wide row
__global__ void k_esum2(const int* __restrict__ src, const int* __restrict__ dst, int e0) {
    int gtid = blockIdx.x * blockDim.x + threadIdx.x;
    int eidx = gtid >> 4;
    int lane16 = gtid & 15;
    if (eidx >= e0) return;
    int s = src[eidx], d = dst[eidx];
    float a = expf(d_e2[eidx] - d_emax2[d]);
    if (lane16 == 0) atomicAdd(&d_denom2[d], a);
    float4 v = ((const float4*)(d_t2 + (size_t)s * 64))[lane16];
    redAdd4(d_num2 + (size_t)d * 64 + lane16 * 4, a * v.x, a * v.y, a * v.z, a * v.w);
}

// mean over nodes of num2/denom2 -> d_acc[64]
__global__ void k_reduce(int n0) {
    int j = threadIdx.x & 63;
    int grp = threadIdx.x >> 6;                  // 0..3
    int nodesPerStep = gridDim.x * (blockDim.x >> 6);
    float local = 0.0f;
    for (int n = blockIdx.x * (blockDim.x >> 6) + grp; n < n0; n += nodesPerStep) {
        float den = fmaxf(d_denom2[n], 1e-9f);
        local += d_num2[(size_t)n * 64 + j] / den;
    }
    __shared__ float sacc[64];
    if (threadIdx.x < 64) sacc[threadIdx.x] = 0.0f;
    __syncthreads();
    atomicAdd(&sacc[j], local);
    __syncthreads();
    if (threadIdx.x < 64) atomicAdd(&d_acc[threadIdx.x], sacc[threadIdx.x]);
}

// dense tail: mean -> relu -> fc1 -> relu -> out
__global__ void k_tail(const float* __restrict__ b2, const float* __restrict__ fc1_w,
                       const float* __restrict__ fc1_b, const float* __restrict__ out_w,
                       const float* __restrict__ out_b, float* __restrict__ out, int n0) {
    __shared__ float hm[64];
    __shared__ float sy[16];
    int t = threadIdx.x;
    if (t < 64) {
        float v = d_acc[t] * (1.0f / (float)n0) + b2[t];
        hm[t] = fmaxf(v, 0.0f);
    }
    __syncthreads();
    if (t < 16) {
        float acc = fc1_b[t];
#pragma unroll
        for (int j = 0; j < 64; j++) acc = fmaf(hm[j], fc1_w[t * 64 + j], acc);
        sy[t] = fmaxf(acc, 0.0f);
    }
    __syncthreads();
    if (t == 0) {
        float o = out_b[0];
#pragma unroll
        for (int i = 0; i < 16; i++) o = fmaf(sy[i], out_w[i], o);
        out[0] = o;
    }
}

// ---------------------------------------------------------------------------
extern "C" void kernel_launch(void* const* d_in, const int* in_sizes, int n_in,
                              void* d_out, int out_size) {
    const float* feat0 = (const float*)d_in[3];
    const int* src0 = (const int*)d_in[4];
    const int* dst0 = (const int*)d_in[5];
    const float* W_rbf0 = (const float*)d_in[9];
    const float* b_rbf0 = (const float*)d_in[10];
    const float* g2c1_W = (const float*)d_in[19];
    const float* g2c1_al = (const float*)d_in[20];
    const float* g2c1_ar = (const float*)d_in[21];
    const float* g2c1_b = (const float*)d_in[22];
    const float* g2c2_W = (const float*)d_in[23];
    const float* g2c2_al = (const float*)d_in[24];
    const float* g2c2_ar = (const float*)d_in[25];
    const float* g2c2_b = (const float*)d_in[26];
    const float* fc1_w = (const float*)d_in[27];
    const float* fc1_b = (const float*)d_in[28];
    const float* out_w = (const float*)d_in[29];
    const float* out_b = (const float*)d_in[30];
    float* out = (float*)d_out;

    int n0 = in_sizes[3] / 62;     // 200000
    int e0 = in_sizes[4];          // 1000000
    if (n0 > N0C) n0 = N0C;
    if (e0 > E0C) e0 = E0C;

    k_init<<<1024, 256>>>(n0);
    k_rbf<<<(n0 + 3) / 4, 256>>>(feat0, W_rbf0, b_rbf0, n0);
    k_t1<<<(n0 + 15) / 16, 256>>>(g2c1_W, g2c1_al, g2c1_ar, n0);
    k_emax1<<<(e0 + 255) / 256, 256>>>(src0, dst0, e0);
    k_esum1<<<(e0 + 255) / 256, 256>>>(src0, dst0, e0);
    k_x1<<<(n0 * 16 + 255) / 256, 256>>>(g2c1_b, n0);
    k_t2<<<(n0 + 3) / 4, 256>>>(g2c2_W, g2c2_al, g2c2_ar, n0);
    k_emax2<<<(e0 + 255) / 256, 256>>>(src0, dst0, e0);
    k_esum2<<<(e0 * 16 + 255) / 256, 256>>>(src0, dst0, e0);
    k_reduce<<<1024, 256>>>(n0);
    k_tail<<<1, 64>>>(g2c2_b, fc1_w, fc1_b, out_w, out_b, out, n0);
}

// round 2
// speedup vs baseline: 1.0599x; 1.0599x over previous
#include <cuda_runtime.h>
#include <cuda_bf16.h>
#include <cstdint>

// ---------------------------------------------------------------------------
// Only the g_list[0] branch matters (g_list[1] branch is dead code).
// Pipeline (max-subtraction removed — softmax is shift-invariant and the
// attention logits are O(0.1), so exp() is safe):
//   k_init     : zero denom1/num1/denom2/acc
//   k_rbf_t1   : nf0 = rbf(feat0) in smem -> t1 = nf0@W1, el1, er1   (nf0 never hits HBM)
//   k_edge1    : a = exp(leaky(el1[s]+er1[d])); scatter denom1, num1 (red.v2/v4)
//   k_t2       : x1 = relu(num1/denom1 + b1) in smem -> t2 = x1@W2, el2, er2
//   k_edge2a   : a = exp(leaky(el2[s]+er2[d])); stash a; scatter denom2 (scalar)
//   k_edge2b   : acc[64] += (a/denom2[d]) * t2[src]   (pure reduction, no num2!)
//   k_tail     : mean -> relu -> fc1 -> relu -> out
// ---------------------------------------------------------------------------

#define N0C 200000
#define E0C 1000000

__device__ __align__(16) float d_t1[(size_t)N0C * 16];
__device__ __align__(8)  float d_el1[N0C * 2];
__device__ __align__(8)  float d_er1[N0C * 2];
__device__ __align__(8)  float d_denom1[N0C * 2];
__device__ __align__(16) float d_num1[(size_t)N0C * 16];
__device__ __align__(16) float d_t2[(size_t)N0C * 64];
__device__ float d_el2[N0C];
__device__ float d_er2[N0C];
__device__ float d_denom2[N0C];
__device__ float d_a2[E0C];
__device__ float d_acc[64];

__device__ __forceinline__ void redAdd4(float* addr, float x, float y, float z, float w) {
    asm volatile("red.global.add.v4.f32 [%0], {%1, %2, %3, %4};"
                 :: "l"(addr), "f"(x), "f"(y), "f"(z), "f"(w) : "memory");
}
__device__ __forceinline__ void redAdd2(float* addr, float x, float y) {
    asm volatile("red.global.add.v2.f32 [%0], {%1, %2};"
                 :: "l"(addr), "f"(x), "f"(y) : "memory");
}
__device__ __forceinline__ float leaky02(float x) {
    return x >= 0.0f ? x : 0.2f * x;
}

// ---------------------------------------------------------------------------
__global__ void k_init(int n0) {
    int i = blockIdx.x * blockDim.x + threadIdx.x;
    int stride = gridDim.x * blockDim.x;
    for (int k = i; k < n0 * 2; k += stride) d_denom1[k] = 0.0f;
    for (int k = i; k < n0; k += stride) d_denom2[k] = 0.0f;
    for (int k = i; k < n0 * 16; k += stride) d_num1[k] = 0.0f;
    if (i < 64) d_acc[i] = 0.0f;
}

// Fused RBF + conv1 node transform. block = 256, 16 nodes per block.
// nf0 lives only in shared memory.
__global__ void k_rbf_t1(const float* __restrict__ feat0, const float* __restrict__ Wrbf,
                         const float* __restrict__ brbf, const float* __restrict__ W1,
                         const float* __restrict__ al, const float* __restrict__ ar, int n0) {
    __shared__ float sfeat[16][62];
    __shared__ float sW[62 * 64];
    __shared__ float snf[16][64];
    __shared__ float sW1[64 * 16];
    __shared__ float st[16][17];
    int tid = threadIdx.x;
    int nodeBase = blockIdx.x * 16;
    for (int i = tid; i < 62 * 64; i += 256) sW[i] = Wrbf[i];
    for (int i = tid; i < 64 * 16; i += 256) sW1[i] = W1[i];
    for (int i = tid; i < 16 * 62; i += 256) {
        int nn = i / 62, kk = i % 62;
        int nd = nodeBase + nn;
        sfeat[nn][kk] = (nd < n0) ? feat0[(size_t)nd * 62 + kk] : 0.0f;
    }
    __syncthreads();
#pragma unroll
    for (int q = 0; q < 4; q++) {
        int idx = tid + q * 256;
        int nn = idx >> 6, j = idx & 63;
        float acc = brbf[j];
#pragma unroll
        for (int k = 0; k < 62; k++) acc = fmaf(sfeat[nn][k], sW[k * 64 + j], acc);
        snf[nn][j] = 0.17677669529663687f * cosf(acc);
    }
    __syncthreads();
    int nn = tid >> 4, hf = tid & 15;
    int node = nodeBase + nn;
    float acc = 0.0f;
#pragma unroll
    for (int k = 0; k < 64; k++) acc = fmaf(snf[nn][k], sW1[k * 16 + hf], acc);
    st[nn][hf] = acc;
    if (node < n0) d_t1[(size_t)node * 16 + hf] = acc;
    __syncthreads();
    if (hf < 2 && node < n0) {
        float el = 0.0f, er = 0.0f;
#pragma unroll
        for (int f = 0; f < 8; f++) {
            float t = st[nn][hf * 8 + f];
            el = fmaf(t, al[hf * 8 + f], el);
            er = fmaf(t, ar[hf * 8 + f], er);
        }
        d_el1[node * 2 + hf] = el;
        d_er1[node * 2 + hf] = er;
    }
}

// conv1 single edge pass: a = exp(leaky(el+er)); scatter denom (v2) + num (4x v4)
__global__ void k_edge1(const int* __restrict__ src, const int* __restrict__ dst, int e0) {
    int i = blockIdx.x * blockDim.x + threadIdx.x;
    if (i >= e0) return;
    int s = src[i], d = dst[i];
    float2 el = *(const float2*)(d_el1 + (size_t)s * 2);
    float2 er = *(const float2*)(d_er1 + (size_t)d * 2);
    float a0 = expf(leaky02(el.x + er.x));
    float a1 = expf(leaky02(el.y + er.y));
    redAdd2(d_denom1 + (size_t)d * 2, a0, a1);
    const float4* tp = (const float4*)(d_t1 + (size_t)s * 16);
    float4 v0 = tp[0], v1 = tp[1], v2 = tp[2], v3 = tp[3];
    float* np = d_num1 + (size_t)d * 16;
    redAdd4(np,      a0 * v0.x, a0 * v0.y, a0 * v0.z, a0 * v0.w);
    redAdd4(np + 4,  a0 * v1.x, a0 * v1.y, a0 * v1.z, a0 * v1.w);
    redAdd4(np + 8,  a1 * v2.x, a1 * v2.y, a1 * v2.z, a1 * v2.w);
    redAdd4(np + 12, a1 * v3.x, a1 * v3.y, a1 * v3.z, a1 * v3.w);
}

// conv2 node transform, with conv1 epilogue fused (x1 never hits HBM).
// block = 256 = 4 nodes x 64 cols.
__global__ void k_t2(const float* __restrict__ W2, const float* __restrict__ al2,
                     const float* __restrict__ ar2, const float* __restrict__ b1, int n0) {
    __shared__ float sx[4][16];
    __shared__ float spart[4][2][2];
    int grp = threadIdx.x >> 6;
    int j = threadIdx.x & 63;
    int node = blockIdx.x * 4 + grp;
    if (threadIdx.x < 64) {
        int nn = threadIdx.x >> 4, kk = threadIdx.x & 15;
        int nd = blockIdx.x * 4 + nn;
        float v = 0.0f;
        if (nd < n0) {
            float den = fmaxf(d_denom1[(size_t)nd * 2 + (kk >> 3)], 1e-9f);
            v = fmaxf(d_num1[(size_t)nd * 16 + kk] / den + b1[kk], 0.0f);
        }
        sx[nn][kk] = v;
    }
    __syncthreads();
    float acc = 0.0f;
#pragma unroll
    for (int k = 0; k < 16; k++) acc = fmaf(sx[grp][k], W2[k * 64 + j], acc);
    if (node < n0) d_t2[(size_t)node * 64 + j] = acc;
    float pl = acc * al2[j], pr = acc * ar2[j];
#pragma unroll
    for (int off = 16; off; off >>= 1) {
        pl += __shfl_down_sync(0xffffffffu, pl, off);
        pr += __shfl_down_sync(0xffffffffu, pr, off);
    }
    int half = j >> 5;
    if ((threadIdx.x & 31) == 0) { spart[grp][half][0] = pl; spart[grp][half][1] = pr; }
    __syncthreads();
    if (j == 0 && node < n0) {
        d_el2[node] = spart[grp][0][0] + spart[grp][1][0];
        d_er2[node] = spart[grp][0][1] + spart[grp][1][1];
    }
}

// conv2 edge pass A: a = exp(leaky(el2[s]+er2[d])); stash a; scalar denom atomic
__global__ void k_edge2a(const int* __restrict__ src, const int* __restrict__ dst, int e0) {
    int i = blockIdx.x * blockDim.x + threadIdx.x;
    if (i >= e0) return;
    int s = src[i], d = dst[i];
    float a = expf(leaky02(d_el2[s] + d_er2[d]));
    d_a2[i] = a;
    atomicAdd(&d_denom2[d], a);
}

// conv2 edge pass B: acc[64] += (a/denom[d]) * t2[src]. Pure reduction into
// registers; 16 lanes per edge (one float4 each); persistent grid-stride.
__global__ void k_edge2b(const int* __restrict__ src, const int* __restrict__ dst, int e0) {
    int lane16 = threadIdx.x & 15;
    int slot = threadIdx.x >> 4;                  // 0..15
    int step = gridDim.x * 16;
    float4 acc = make_float4(0.0f, 0.0f, 0.0f, 0.0f);
    for (int e = blockIdx.x * 16 + slot; e < e0; e += step) {
        int s = 0;
        float c = 0.0f;
        if (lane16 == 0) {
            s = src[e];
            int d = dst[e];
            c = d_a2[e] / fmaxf(d_denom2[d], 1e-9f);
        }
        s = __shfl_sync(0xffffffffu, s, 0, 16);
        c = __shfl_sync(0xffffffffu, c, 0, 16);
        float4 v = ((const float4*)(d_t2 + (size_t)s * 64))[lane16];
        acc.x = fmaf(c, v.x, acc.x);
        acc.y = fmaf(c, v.y, acc.y);
        acc.z = fmaf(c, v.z, acc.z);
        acc.w = fmaf(c, v.w, acc.w);
    }
    __shared__ float sacc[64];
    if (threadIdx.x < 64) sacc[threadIdx.x] = 0.0f;
    __syncthreads();
    atomicAdd(&sacc[lane16 * 4 + 0], acc.x);
    atomicAdd(&sacc[lane16 * 4 + 1], acc.y);
    atomicAdd(&sacc[lane16 * 4 + 2], acc.z);
    atomicAdd(&sacc[lane16 * 4 + 3], acc.w);
    __syncthreads();
    if (threadIdx.x < 64) atomicAdd(&d_acc[threadIdx.x], sacc[threadIdx.x]);
}

// dense tail: mean -> relu -> fc1 -> relu -> out
__global__ void k_tail(const float* __restrict__ b2, const float* __restrict__ fc1_w,
                       const float* __restrict__ fc1_b, const float* __restrict__ out_w,
                       const float* __restrict__ out_b, float* __restrict__ out, int n0) {
    __shared__ float hm[64];
    __shared__ float sy[16];
    int t = threadIdx.x;
    if (t < 64) {
        float v = d_acc[t] * (1.0f / (float)n0) + b2[t];
        hm[t] = fmaxf(v, 0.0f);
    }
    __syncthreads();
    if (t < 16) {
        float acc = fc1_b[t];
#pragma unroll
        for (int j = 0; j < 64; j++) acc = fmaf(hm[j], fc1_w[t * 64 + j], acc);
        sy[t] = fmaxf(acc, 0.0f);
    }
    __syncthreads();
    if (t == 0) {
        float o = out_b[0];
#pragma unroll
        for (int i = 0; i < 16; i++) o = fmaf(sy[i], out_w[i], o);
        out[0] = o;
    }
}

// ---------------------------------------------------------------------------
extern "C" void kernel_launch(void* const* d_in, const int* in_sizes, int n_in,
                              void* d_out, int out_size) {
    const float* feat0 = (const float*)d_in[3];
    const int* src0 = (const int*)d_in[4];
    const int* dst0 = (const int*)d_in[5];
    const float* W_rbf0 = (const float*)d_in[9];
    const float* b_rbf0 = (const float*)d_in[10];
    const float* g2c1_W = (const float*)d_in[19];
    const float* g2c1_al = (const float*)d_in[20];
    const float* g2c1_ar = (const float*)d_in[21];
    const float* g2c1_b = (const float*)d_in[22];
    const float* g2c2_W = (const float*)d_in[23];
    const float* g2c2_al = (const float*)d_in[24];
    const float* g2c2_ar = (const float*)d_in[25];
    const float* g2c2_b = (const float*)d_in[26];
    const float* fc1_w = (const float*)d_in[27];
    const float* fc1_b = (const float*)d_in[28];
    const float* out_w = (const float*)d_in[29];
    const float* out_b = (const float*)d_in[30];
    float* out = (float*)d_out;

    int n0 = in_sizes[3] / 62;     // 200000
    int e0 = in_sizes[4];          // 1000000
    if (n0 > N0C) n0 = N0C;
    if (e0 > E0C) e0 = E0C;

    k_init<<<592, 256>>>(n0);
    k_rbf_t1<<<(n0 + 15) / 16, 256>>>(feat0, W_rbf0, b_rbf0, g2c1_W, g2c1_al, g2c1_ar, n0);
    k_edge1<<<(e0 + 255) / 256, 256>>>(src0, dst0, e0);
    k_t2<<<(n0 + 3) / 4, 256>>>(g2c2_W, g2c2_al, g2c2_ar, g2c1_b, n0);
    k_edge2a<<<(e0 + 255) / 256, 256>>>(src0, dst0, e0);
    k_edge2b<<<592, 256>>>(src0, dst0, e0);
    k_tail<<<1, 64>>>(g2c2_b, fc1_w, fc1_b, out_w, out_b, out, n0);
}

// round 3
// speedup vs baseline: 1.3949x; 1.3161x over previous
#include <cuda_runtime.h>
#include <cuda_bf16.h>
#include <cstdint>

// ---------------------------------------------------------------------------
// Only the g_list[0] branch matters (g_list[1] branch is dead code).
//   k_init    : zero denom1/num1/denom2/acc
//   k_rbf_t1  : nf0 = rbf(feat0) in smem -> t1 = nf0@W1, el1, er1  (packed f32x2)
//   k_edge1   : a = exp(leaky(el1[s]+er1[d])); scatter denom1, num1 (red.v2/v4)
//   k_t2      : x1 = relu(num1/denom1+b1) -> t2 = x1@W2 (1 node/thread, f32x2),
//               el2/er2 via wl/wr = W2@al2 / W2@ar2 trick
//   k_edge2a  : a = exp(leaky(el2[s]+er2[d])); stash a; scalar denom2 atomic
//   k_rcp     : denom2 <- 1/max(denom2,1e-9)
//   k_edge2b  : acc[64] += (a*rdenom[d]) * t2[src]   (pure reduction, no num2)
//   k_tail    : mean -> relu -> fc1 -> relu -> out
// Softmax max-subtraction removed (shift-invariant; logits are O(0.1)).
// ---------------------------------------------------------------------------

#define N0C 200000
#define E0C 1000000

typedef unsigned long long ull;

__device__ __align__(16) float d_t1[(size_t)N0C * 16];
__device__ __align__(8)  float d_el1[N0C * 2];
__device__ __align__(8)  float d_er1[N0C * 2];
__device__ __align__(8)  float d_denom1[N0C * 2];
__device__ __align__(16) float d_num1[(size_t)N0C * 16];
__device__ __align__(16) float d_t2[(size_t)N0C * 64];
__device__ float d_el2[N0C];
__device__ float d_er2[N0C];
__device__ float d_denom2[N0C];
__device__ float d_a2[E0C];
__device__ float d_acc[64];

__device__ __forceinline__ void redAdd4(float* addr, float x, float y, float z, float w) {
    asm volatile("red.global.add.v4.f32 [%0], {%1, %2, %3, %4};"
                 :: "l"(addr), "f"(x), "f"(y), "f"(z), "f"(w) : "memory");
}
__device__ __forceinline__ void redAdd2(float* addr, float x, float y) {
    asm volatile("red.global.add.v2.f32 [%0], {%1, %2};"
                 :: "l"(addr), "f"(x), "f"(y) : "memory");
}
__device__ __forceinline__ float leaky02(float x) {
    return x >= 0.0f ? x : 0.2f * x;
}
__device__ __forceinline__ ull pk2(float lo, float hi) {
    ull r; asm("mov.b64 %0, {%1, %2};" : "=l"(r) : "f"(lo), "f"(hi)); return r;
}
__device__ __forceinline__ void upk2(float& lo, float& hi, ull v) {
    asm("mov.b64 {%0, %1}, %2;" : "=f"(lo), "=f"(hi) : "l"(v));
}
__device__ __forceinline__ ull fma2(ull a, ull b, ull c) {
    ull d; asm("fma.rn.f32x2 %0, %1, %2, %3;" : "=l"(d) : "l"(a), "l"(b), "l"(c)); return d;
}

// ---------------------------------------------------------------------------
__global__ void k_init(int n0) {
    int i = blockIdx.x * blockDim.x + threadIdx.x;
    int stride = gridDim.x * blockDim.x;
    for (int k = i; k < n0 * 2; k += stride) d_denom1[k] = 0.0f;
    for (int k = i; k < n0; k += stride) d_denom2[k] = 0.0f;
    for (int k = i; k < n0 * 16; k += stride) d_num1[k] = 0.0f;
    if (i < 64) d_acc[i] = 0.0f;
}

// Fused RBF + conv1 node transform. block = 256; 16 nodes/block;
// phase 1: thread = (node nn = tid>>4, 4 j-cols at (tid&15)*4), packed f32x2.
__global__ void k_rbf_t1(const float* __restrict__ feat0, const float* __restrict__ Wrbf,
                         const float* __restrict__ brbf, const float* __restrict__ W1,
                         const float* __restrict__ al, const float* __restrict__ ar, int n0) {
    __shared__ float sfeat[16][62];
    __shared__ float4 sW4[62 * 16];   // W_rbf [k][j4-group]
    __shared__ float snf[16][64];
    __shared__ float sW1[64 * 16];
    __shared__ float st[16][17];
    __shared__ float sb[64];
    int tid = threadIdx.x;
    int nodeBase = blockIdx.x * 16;
    for (int i = tid; i < 62 * 16; i += 256) sW4[i] = ((const float4*)Wrbf)[i];
    for (int i = tid; i < 64 * 16; i += 256) sW1[i] = W1[i];
    if (tid < 64) sb[tid] = brbf[tid];
    for (int i = tid; i < 16 * 62; i += 256) {
        int nn = i / 62, kk = i % 62;
        int nd = nodeBase + nn;
        sfeat[nn][kk] = (nd < n0) ? feat0[(size_t)nd * 62 + kk] : 0.0f;
    }
    __syncthreads();

    int nn = tid >> 4;
    int jg = tid & 15;          // j-group; j = jg*4 .. jg*4+3
    ull acc01 = pk2(sb[jg * 4 + 0], sb[jg * 4 + 1]);
    ull acc23 = pk2(sb[jg * 4 + 2], sb[jg * 4 + 3]);
#pragma unroll
    for (int k = 0; k < 62; k++) {
        float f = sfeat[nn][k];
        ull ff = pk2(f, f);
        ulonglong2 w = *reinterpret_cast<const ulonglong2*>(&sW4[k * 16 + jg]);
        acc01 = fma2(ff, w.x, acc01);
        acc23 = fma2(ff, w.y, acc23);
    }
    float a0, a1, a2, a3;
    upk2(a0, a1, acc01);
    upk2(a2, a3, acc23);
    const float SC = 0.17677669529663687f;
    float4 nf4;
    nf4.x = SC * __cosf(a0);
    nf4.y = SC * __cosf(a1);
    nf4.z = SC * __cosf(a2);
    nf4.w = SC * __cosf(a3);
    *reinterpret_cast<float4*>(&snf[nn][jg * 4]) = nf4;
    __syncthreads();

    // phase 2: t1 = nf @ W1. thread = (nn, hf)
    int hf = jg;
    float acc = 0.0f;
#pragma unroll
    for (int k = 0; k < 64; k++) acc = fmaf(snf[nn][k], sW1[k * 16 + hf], acc);
    st[nn][hf] = acc;
    int node = nodeBase + nn;
    if (node < n0) d_t1[(size_t)node * 16 + hf] = acc;   // coalesced
    __syncthreads();
    if (hf < 2 && node < n0) {
        float el = 0.0f, er = 0.0f;
#pragma unroll
        for (int f = 0; f < 8; f++) {
            float t = st[nn][hf * 8 + f];
            el = fmaf(t, al[hf * 8 + f], el);
            er = fmaf(t, ar[hf * 8 + f], er);
        }
        d_el1[node * 2 + hf] = el;
        d_er1[node * 2 + hf] = er;
    }
}

// conv1 single edge pass: a = exp(leaky(el+er)); scatter denom (v2) + num (4x v4)
__global__ void k_edge1(const int* __restrict__ src, const int* __restrict__ dst, int e0) {
    int i = blockIdx.x * blockDim.x + threadIdx.x;
    if (i >= e0) return;
    int s = src[i], d = dst[i];
    float2 el = *(const float2*)(d_el1 + (size_t)s * 2);
    float2 er = *(const float2*)(d_er1 + (size_t)d * 2);
    float a0 = __expf(leaky02(el.x + er.x));
    float a1 = __expf(leaky02(el.y + er.y));
    redAdd2(d_denom1 + (size_t)d * 2, a0, a1);
    const float4* tp = (const float4*)(d_t1 + (size_t)s * 16);
    float4 v0 = tp[0], v1 = tp[1], v2 = tp[2], v3 = tp[3];
    float* np = d_num1 + (size_t)d * 16;
    redAdd4(np,      a0 * v0.x, a0 * v0.y, a0 * v0.z, a0 * v0.w);
    redAdd4(np + 4,  a0 * v1.x, a0 * v1.y, a0 * v1.z, a0 * v1.w);
    redAdd4(np + 8,  a1 * v2.x, a1 * v2.y, a1 * v2.z, a1 * v2.w);
    redAdd4(np + 12, a1 * v3.x, a1 * v3.y, a1 * v3.z, a1 * v3.w);
}

// conv2 node transform, conv1 epilogue fused. One node per thread, packed f32x2.
__global__ void k_t2(const float* __restrict__ W2, const float* __restrict__ al2,
                     const float* __restrict__ ar2, const float* __restrict__ b1, int n0) {
    __shared__ float4 sW2[16 * 16];   // W2 [k][j4-group]
    __shared__ float swl[16], swr[16], sb1[16];
    int tid = threadIdx.x;
    if (tid < 256) {
        if (tid < 16 * 16) sW2[tid] = ((const float4*)W2)[tid];
    }
    if (tid < 16) sb1[tid] = b1[tid];
    if (tid < 32) {
        int h = tid & 15;
        const float* av = (tid >= 16) ? ar2 : al2;
        float a = 0.0f;
#pragma unroll
        for (int j = 0; j < 64; j++) a = fmaf(W2[h * 64 + j], av[j], a);
        if (tid >= 16) swr[h] = a; else swl[h] = a;
    }
    __syncthreads();
    int node = blockIdx.x * blockDim.x + tid;
    if (node >= n0) return;

    float2 dn = *(const float2*)(d_denom1 + (size_t)node * 2);
    float r0 = 1.0f / fmaxf(dn.x, 1e-9f);
    float r1 = 1.0f / fmaxf(dn.y, 1e-9f);
    const float4* np = (const float4*)(d_num1 + (size_t)node * 16);
    float x[16];
#pragma unroll
    for (int q = 0; q < 4; q++) {
        float4 v = np[q];
        float r = (q < 2) ? r0 : r1;
        x[q * 4 + 0] = fmaxf(fmaf(v.x, r, sb1[q * 4 + 0]), 0.0f);
        x[q * 4 + 1] = fmaxf(fmaf(v.y, r, sb1[q * 4 + 1]), 0.0f);
        x[q * 4 + 2] = fmaxf(fmaf(v.z, r, sb1[q * 4 + 2]), 0.0f);
        x[q * 4 + 3] = fmaxf(fmaf(v.w, r, sb1[q * 4 + 3]), 0.0f);
    }
    ull acc[32];
#pragma unroll
    for (int i = 0; i < 32; i++) acc[i] = 0ULL;
    float el = 0.0f, er = 0.0f;
#pragma unroll
    for (int k = 0; k < 16; k++) {
        ull xx = pk2(x[k], x[k]);
#pragma unroll
        for (int jg = 0; jg < 16; jg++) {
            ulonglong2 w = *reinterpret_cast<const ulonglong2*>(&sW2[k * 16 + jg]);
            acc[2 * jg]     = fma2(xx, w.x, acc[2 * jg]);
            acc[2 * jg + 1] = fma2(xx, w.y, acc[2 * jg + 1]);
        }
        el = fmaf(x[k], swl[k], el);
        er = fmaf(x[k], swr[k], er);
    }
    float4* orow = (float4*)(d_t2 + (size_t)node * 64);
#pragma unroll
    for (int jg = 0; jg < 16; jg++) {
        float4 o;
        upk2(o.x, o.y, acc[2 * jg]);
        upk2(o.z, o.w, acc[2 * jg + 1]);
        orow[jg] = o;
    }
    d_el2[node] = el;
    d_er2[node] = er;
}

// conv2 edge pass A: a = exp(leaky(el2[s]+er2[d])); stash a; scalar denom atomic
__global__ void k_edge2a(const int* __restrict__ src, const int* __restrict__ dst, int e0) {
    int i = blockIdx.x * blockDim.x + threadIdx.x;
    if (i >= e0) return;
    int s = src[i], d = dst[i];
    float a = __expf(leaky02(d_el2[s] + d_er2[d]));
    d_a2[i] = a;
    atomicAdd(&d_denom2[d], a);
}

__global__ void k_rcp(int n0) {
    int i = blockIdx.x * blockDim.x + threadIdx.x;
    if (i < n0) d_denom2[i] = 1.0f / fmaxf(d_denom2[i], 1e-9f);
}

// conv2 edge pass B: acc[64] += (a*rdenom[d]) * t2[src]. Pure reduction.
__global__ void k_edge2b(const int* __restrict__ src, const int* __restrict__ dst, int e0) {
    int lane16 = threadIdx.x & 15;
    int slot = threadIdx.x >> 4;                  // 0..15
    int step = gridDim.x * 16;
    float4 acc = make_float4(0.0f, 0.0f, 0.0f, 0.0f);
    for (int e = blockIdx.x * 16 + slot; e < e0; e += step) {
        int s = 0;
        float c = 0.0f;
        if (lane16 == 0) {
            s = src[e];
            int d = dst[e];
            c = d_a2[e] * d_denom2[d];
        }
        s = __shfl_sync(0xffffffffu, s, 0, 16);
        c = __shfl_sync(0xffffffffu, c, 0, 16);
        float4 v = ((const float4*)(d_t2 + (size_t)s * 64))[lane16];
        acc.x = fmaf(c, v.x, acc.x);
        acc.y = fmaf(c, v.y, acc.y);
        acc.z = fmaf(c, v.z, acc.z);
        acc.w = fmaf(c, v.w, acc.w);
    }
    __shared__ float sacc[64];
    if (threadIdx.x < 64) sacc[threadIdx.x] = 0.0f;
    __syncthreads();
    atomicAdd(&sacc[lane16 * 4 + 0], acc.x);
    atomicAdd(&sacc[lane16 * 4 + 1], acc.y);
    atomicAdd(&sacc[lane16 * 4 + 2], acc.z);
    atomicAdd(&sacc[lane16 * 4 + 3], acc.w);
    __syncthreads();
    if (threadIdx.x < 64) atomicAdd(&d_acc[threadIdx.x], sacc[threadIdx.x]);
}

// dense tail: mean -> relu -> fc1 -> relu -> out
__global__ void k_tail(const float* __restrict__ b2, const float* __restrict__ fc1_w,
                       const float* __restrict__ fc1_b, const float* __restrict__ out_w,
                       const float* __restrict__ out_b, float* __restrict__ out, int n0) {
    __shared__ float hm[64];
    __shared__ float sy[16];
    int t = threadIdx.x;
    if (t < 64) {
        float v = d_acc[t] * (1.0f / (float)n0) + b2[t];
        hm[t] = fmaxf(v, 0.0f);
    }
    __syncthreads();
    if (t < 16) {
        float acc = fc1_b[t];
#pragma unroll
        for (int j = 0; j < 64; j++) acc = fmaf(hm[j], fc1_w[t * 64 + j], acc);
        sy[t] = fmaxf(acc, 0.0f);
    }
    __syncthreads();
    if (t == 0) {
        float o = out_b[0];
#pragma unroll
        for (int i = 0; i < 16; i++) o = fmaf(sy[i], out_w[i], o);
        out[0] = o;
    }
}

// ---------------------------------------------------------------------------
extern "C" void kernel_launch(void* const* d_in, const int* in_sizes, int n_in,
                              void* d_out, int out_size) {
    const float* feat0 = (const float*)d_in[3];
    const int* src0 = (const int*)d_in[4];
    const int* dst0 = (const int*)d_in[5];
    const float* W_rbf0 = (const float*)d_in[9];
    const float* b_rbf0 = (const float*)d_in[10];
    const float* g2c1_W = (const float*)d_in[19];
    const float* g2c1_al = (const float*)d_in[20];
    const float* g2c1_ar = (const float*)d_in[21];
    const float* g2c1_b = (const float*)d_in[22];
    const float* g2c2_W = (const float*)d_in[23];
    const float* g2c2_al = (const float*)d_in[24];
    const float* g2c2_ar = (const float*)d_in[25];
    const float* g2c2_b = (const float*)d_in[26];
    const float* fc1_w = (const float*)d_in[27];
    const float* fc1_b = (const float*)d_in[28];
    const float* out_w = (const float*)d_in[29];
    const float* out_b = (const float*)d_in[30];
    float* out = (float*)d_out;

    int n0 = in_sizes[3] / 62;     // 200000
    int e0 = in_sizes[4];          // 1000000
    if (n0 > N0C) n0 = N0C;
    if (e0 > E0C) e0 = E0C;

    k_init<<<592, 256>>>(n0);
    k_rbf_t1<<<(n0 + 15) / 16, 256>>>(feat0, W_rbf0, b_rbf0, g2c1_W, g2c1_al, g2c1_ar, n0);
    k_edge1<<<(e0 + 255) / 256, 256>>>(src0, dst0, e0);
    k_t2<<<(n0 + 255) / 256, 256>>>(g2c2_W, g2c2_al, g2c2_ar, g2c1_b, n0);
    k_edge2a<<<(e0 + 255) / 256, 256>>>(src0, dst0, e0);
    k_rcp<<<(n0 + 255) / 256, 256>>>(n0);
    k_edge2b<<<592, 256>>>(src0, dst0, e0);
    k_tail<<<1, 64>>>(g2c2_b, fc1_w, fc1_b, out_w, out_b, out, n0);
}